// round 3
// baseline (speedup 1.0000x reference)
#include <cuda_runtime.h>

#define N_USERS 100000
#define N_ITEMS 50000
#define N_NODES 150000           // N_USERS + N_ITEMS
#define D_VEC4 16                // 64 floats = 16 float4
#define NNZ_E 4800000
#define BATCH 16384
#define SCAN_BLK 1024
#define NBLK_SCAN 147            // ceil(150000/1024)

// ---------------- scratch (device globals; no allocation allowed) -----------
__device__ float4 g_emb0[N_NODES * D_VEC4];   // 38.4 MB
__device__ float4 g_emb1[N_NODES * D_VEC4];   // 38.4 MB
__device__ float4 g_acc [N_NODES * D_VEC4];   // 38.4 MB
__device__ int    g_cnt [N_NODES];
__device__ int    g_fill[N_NODES];
__device__ int    g_rowptr[N_NODES + 1];
__device__ int    g_bsum[SCAN_BLK];
__device__ int2   g_pedge[NNZ_E];             // {col, val-as-int}  38.4 MB
__device__ int    g_is64;

// ---------------- setup kernels ---------------------------------------------
__global__ void k_zero_counts() {
    int i = blockIdx.x * blockDim.x + threadIdx.x;
    if (i < N_NODES) { g_cnt[i] = 0; g_fill[i] = 0; }
}

__global__ void k_init(const float4* __restrict__ ue, const float4* __restrict__ ie) {
    int i = blockIdx.x * blockDim.x + threadIdx.x;   // over N_NODES*16 float4
    if (i >= N_NODES * D_VEC4) return;
    int node = i >> 4;
    float4 v = (node < N_USERS) ? ue[i] : ie[i - N_USERS * D_VEC4];
    g_emb0[i] = v;
    g_acc[i]  = v;
}

__global__ void k_detect_idx_width(const int* __restrict__ p) {
    // If data is int64 (values < 2^31), every odd 32-bit word is 0.
    // 32 independent checks -> false positive prob ~ (1e-5)^32 for real int32 data.
    if (blockIdx.x == 0 && threadIdx.x == 0) {
        int all0 = 1;
        #pragma unroll
        for (int k = 1; k < 64; k += 2) if (p[k] != 0) all0 = 0;
        g_is64 = all0;
    }
}

// ---------------- CSR build: histogram -> scan -> scatter --------------------
__global__ void k_hist(const int* __restrict__ rows) {
    int e = blockIdx.x * blockDim.x + threadIdx.x;
    if (e < NNZ_E) atomicAdd(&g_cnt[rows[e]], 1);
}

__global__ void k_scanA() {
    __shared__ int s[SCAN_BLK];
    int t = threadIdx.x;
    int i = blockIdx.x * SCAN_BLK + t;
    int v = (i < N_NODES) ? g_cnt[i] : 0;
    s[t] = v; __syncthreads();
    for (int off = 1; off < SCAN_BLK; off <<= 1) {
        int x = (t >= off) ? s[t - off] : 0;
        __syncthreads();
        s[t] += x;
        __syncthreads();
    }
    if (i < N_NODES) g_rowptr[i] = s[t];            // inclusive, within block
    if (t == SCAN_BLK - 1) g_bsum[blockIdx.x] = s[t];
}

__global__ void k_scanB() {
    __shared__ int s[256];
    int t = threadIdx.x;
    int v = (t < NBLK_SCAN) ? g_bsum[t] : 0;
    s[t] = v; __syncthreads();
    for (int off = 1; off < 256; off <<= 1) {
        int x = (t >= off) ? s[t - off] : 0;
        __syncthreads();
        s[t] += x;
        __syncthreads();
    }
    if (t < NBLK_SCAN) g_bsum[t] = s[t] - v;        // exclusive block offsets
}

__global__ void k_scanC() {
    int i = blockIdx.x * blockDim.x + threadIdx.x;
    if (i < N_NODES)
        g_rowptr[i] = g_rowptr[i] - g_cnt[i] + g_bsum[i >> 10];  // global exclusive
    if (i == 0) g_rowptr[N_NODES] = NNZ_E;
}

__global__ void k_scatter(const int* __restrict__ rows, const int* __restrict__ cols,
                          const float* __restrict__ vals) {
    int e = blockIdx.x * blockDim.x + threadIdx.x;
    if (e >= NNZ_E) return;
    int r = rows[e];
    int pos = g_rowptr[r] + atomicAdd(&g_fill[r], 1);
    g_pedge[pos] = make_int2(cols[e], __float_as_int(vals[e]));
}

// ---------------- SpMM: half-warp per row, register accumulation -------------
__global__ void __launch_bounds__(256) k_spmm(int phase) {
    // phase 0: emb0 -> emb1 ; phase 1: emb1 -> emb0. Always acc += result.
    const float4* __restrict__ src = phase ? g_emb1 : g_emb0;
    float4*       __restrict__ dst = phase ? g_emb0 : g_emb1;

    int t    = blockIdx.x * blockDim.x + threadIdx.x;
    int w    = t >> 5;
    int lane = t & 31;
    int row  = w * 2 + (lane >> 4);       // 2 rows per warp
    int hl   = lane & 15;                 // lane within half-warp
    if (row >= N_NODES) return;

    int start = g_rowptr[row];
    int end   = g_rowptr[row + 1];

    float4 s = make_float4(0.f, 0.f, 0.f, 0.f);
    int j = start;
    for (; j + 1 < end; j += 2) {
        int2 e0 = g_pedge[j];
        int2 e1 = g_pedge[j + 1];
        float4 x0 = __ldg(&src[e0.x * D_VEC4 + hl]);
        float4 x1 = __ldg(&src[e1.x * D_VEC4 + hl]);
        float v0 = __int_as_float(e0.y);
        float v1 = __int_as_float(e1.y);
        s.x += v0 * x0.x; s.y += v0 * x0.y; s.z += v0 * x0.z; s.w += v0 * x0.w;
        s.x += v1 * x1.x; s.y += v1 * x1.y; s.z += v1 * x1.z; s.w += v1 * x1.w;
    }
    if (j < end) {
        int2 e0 = g_pedge[j];
        float4 x0 = __ldg(&src[e0.x * D_VEC4 + hl]);
        float v0 = __int_as_float(e0.y);
        s.x += v0 * x0.x; s.y += v0 * x0.y; s.z += v0 * x0.z; s.w += v0 * x0.w;
    }

    int o = row * D_VEC4 + hl;
    dst[o] = s;
    float4 a = g_acc[o];
    a.x += s.x; a.y += s.y; a.z += s.z; a.w += s.w;
    g_acc[o] = a;
}

// ---------------- epilogue: gather + dot -------------------------------------
__global__ void k_dot(const void* __restrict__ uidx_raw, const void* __restrict__ iidx_raw,
                      float* __restrict__ out) {
    int t    = blockIdx.x * blockDim.x + threadIdx.x;
    int w    = t >> 5;
    int lane = t & 31;
    if (w >= BATCH) return;

    long long u, it;
    if (g_is64) {
        u  = ((const long long*)uidx_raw)[w];
        it = ((const long long*)iidx_raw)[w];
    } else {
        u  = ((const int*)uidx_raw)[w];
        it = ((const int*)iidx_raw)[w];
    }

    const float2* a = (const float2*)g_acc;
    float2 x = a[(size_t)u * 32 + lane];
    float2 y = a[((size_t)N_USERS + (size_t)it) * 32 + lane];
    float p = x.x * y.x + x.y * y.y;
    #pragma unroll
    for (int off = 16; off; off >>= 1)
        p += __shfl_xor_sync(0xffffffffu, p, off);
    if (lane == 0) out[w] = p * (1.0f / 16.0f);   // (acc/4)·(acc/4)
}

// ---------------- launch ------------------------------------------------------
extern "C" void kernel_launch(void* const* d_in, const int* in_sizes, int n_in,
                              void* d_out, int out_size) {
    const float4* ue   = (const float4*)d_in[0];
    const float4* ie   = (const float4*)d_in[1];
    const int*    rows = (const int*)d_in[2];
    const int*    cols = (const int*)d_in[3];
    const float*  vals = (const float*)d_in[4];
    const void*   uidx = d_in[5];
    const void*   iidx = d_in[6];
    float* out = (float*)d_out;

    k_zero_counts<<<(N_NODES + 255) / 256, 256>>>();
    k_init<<<(N_NODES * D_VEC4 + 255) / 256, 256>>>(ue, ie);
    k_detect_idx_width<<<1, 32>>>((const int*)uidx);
    k_hist<<<(NNZ_E + 255) / 256, 256>>>(rows);
    k_scanA<<<NBLK_SCAN, SCAN_BLK>>>();
    k_scanB<<<1, 256>>>();
    k_scanC<<<(N_NODES + 255) / 256, 256>>>();
    k_scatter<<<(NNZ_E + 255) / 256, 256>>>(rows, cols, vals);

    // 3 layers, ping-pong
    k_spmm<<<(N_NODES / 2 * 32 + 255) / 256, 256>>>(0);  // emb0 -> emb1
    k_spmm<<<(N_NODES / 2 * 32 + 255) / 256, 256>>>(1);  // emb1 -> emb0
    k_spmm<<<(N_NODES / 2 * 32 + 255) / 256, 256>>>(0);  // emb0 -> emb1

    k_dot<<<BATCH * 32 / 256, 256>>>(uidx, iidx, out);
}

// round 4
// speedup vs baseline: 1.2947x; 1.2947x over previous
#include <cuda_runtime.h>
#include <cuda_fp16.h>

#define N_USERS 100000
#define N_ITEMS 50000
#define N_NODES 150000           // N_USERS + N_ITEMS
#define D_VEC4 16                // 64 floats = 16 float4 per row
#define H_VEC4 8                 // 64 halfs  = 8 uint4  per row (128B)
#define NNZ_E 4800000
#define BATCH 16384
#define SCAN_BLK 1024
#define NBLK_SCAN 147            // ceil(150000/1024)

// ---------------- scratch (device globals; no allocation allowed) -----------
__device__ uint4  g_h0[N_NODES * H_VEC4];        // fp16 embeddings ping (19.2 MB)
__device__ uint4  g_h1[N_NODES * H_VEC4];        // fp16 embeddings pong (19.2 MB)
__device__ float4 g_o[3][N_NODES * D_VEC4];      // fp32 per-layer outputs (115 MB)
__device__ int    g_cnt [N_NODES];
__device__ int    g_fill[N_NODES];
__device__ int    g_rowptr[N_NODES + 1];
__device__ int    g_bsum[SCAN_BLK];
__device__ int2   g_pedge[NNZ_E];                // {col, val-as-int} 38.4 MB
__device__ int    g_is64;

// ---------------- setup kernels ---------------------------------------------
__global__ void k_zero_counts() {
    int i = blockIdx.x * blockDim.x + threadIdx.x;
    if (i < N_NODES) { g_cnt[i] = 0; g_fill[i] = 0; }
}

// Build fp16 copy of the initial embeddings (layer-0 source for SpMM).
__global__ void k_init(const float4* __restrict__ ue, const float4* __restrict__ ie) {
    int i = blockIdx.x * blockDim.x + threadIdx.x;   // over N_NODES * H_VEC4
    if (i >= N_NODES * H_VEC4) return;
    int node = i >> 3;
    int q    = i & 7;                                // which uint4 within row
    const float4* src = (node < N_USERS) ? ue : ie;
    int base = (node < N_USERS) ? node : (node - N_USERS);
    float4 f0 = src[base * D_VEC4 + q * 2];
    float4 f1 = src[base * D_VEC4 + q * 2 + 1];
    half2 h0 = __float22half2_rn(make_float2(f0.x, f0.y));
    half2 h1 = __float22half2_rn(make_float2(f0.z, f0.w));
    half2 h2 = __float22half2_rn(make_float2(f1.x, f1.y));
    half2 h3 = __float22half2_rn(make_float2(f1.z, f1.w));
    uint4 o;
    o.x = *(unsigned*)&h0; o.y = *(unsigned*)&h1;
    o.z = *(unsigned*)&h2; o.w = *(unsigned*)&h3;
    g_h0[i] = o;
}

__global__ void k_detect_idx_width(const int* __restrict__ p) {
    // int64 indices (< 2^31) => every odd 32-bit word is 0.
    if (blockIdx.x == 0 && threadIdx.x == 0) {
        int all0 = 1;
        #pragma unroll
        for (int k = 1; k < 64; k += 2) if (p[k] != 0) all0 = 0;
        g_is64 = all0;
    }
}

// ---------------- CSR build: histogram -> scan -> scatter --------------------
__global__ void k_hist(const int4* __restrict__ rows4) {
    int i = blockIdx.x * blockDim.x + threadIdx.x;   // over NNZ_E/4
    if (i >= NNZ_E / 4) return;
    int4 r = rows4[i];
    atomicAdd(&g_cnt[r.x], 1);
    atomicAdd(&g_cnt[r.y], 1);
    atomicAdd(&g_cnt[r.z], 1);
    atomicAdd(&g_cnt[r.w], 1);
}

__global__ void k_scanA() {
    __shared__ int s[SCAN_BLK];
    int t = threadIdx.x;
    int i = blockIdx.x * SCAN_BLK + t;
    int v = (i < N_NODES) ? g_cnt[i] : 0;
    s[t] = v; __syncthreads();
    for (int off = 1; off < SCAN_BLK; off <<= 1) {
        int x = (t >= off) ? s[t - off] : 0;
        __syncthreads();
        s[t] += x;
        __syncthreads();
    }
    if (i < N_NODES) g_rowptr[i] = s[t];            // inclusive, within block
    if (t == SCAN_BLK - 1) g_bsum[blockIdx.x] = s[t];
}

__global__ void k_scanB() {
    __shared__ int s[256];
    int t = threadIdx.x;
    int v = (t < NBLK_SCAN) ? g_bsum[t] : 0;
    s[t] = v; __syncthreads();
    for (int off = 1; off < 256; off <<= 1) {
        int x = (t >= off) ? s[t - off] : 0;
        __syncthreads();
        s[t] += x;
        __syncthreads();
    }
    if (t < NBLK_SCAN) g_bsum[t] = s[t] - v;        // exclusive block offsets
}

__global__ void k_scanC() {
    int i = blockIdx.x * blockDim.x + threadIdx.x;
    if (i < N_NODES)
        g_rowptr[i] = g_rowptr[i] - g_cnt[i] + g_bsum[i >> 10];  // global exclusive
    if (i == 0) g_rowptr[N_NODES] = NNZ_E;
}

__global__ void k_scatter(const int4* __restrict__ rows4, const int4* __restrict__ cols4,
                          const float4* __restrict__ vals4) {
    int i = blockIdx.x * blockDim.x + threadIdx.x;   // over NNZ_E/4
    if (i >= NNZ_E / 4) return;
    int4   r = rows4[i];
    int4   c = cols4[i];
    float4 v = vals4[i];
    int p;
    p = g_rowptr[r.x] + atomicAdd(&g_fill[r.x], 1); g_pedge[p] = make_int2(c.x, __float_as_int(v.x));
    p = g_rowptr[r.y] + atomicAdd(&g_fill[r.y], 1); g_pedge[p] = make_int2(c.y, __float_as_int(v.y));
    p = g_rowptr[r.z] + atomicAdd(&g_fill[r.z], 1); g_pedge[p] = make_int2(c.z, __float_as_int(v.z));
    p = g_rowptr[r.w] + atomicAdd(&g_fill[r.w], 1); g_pedge[p] = make_int2(c.w, __float_as_int(v.w));
}

// ---------------- SpMM: quarter-warp per row, fp16 gather, fp32 accum --------
__device__ __forceinline__ void fma_edge(float2& a0, float2& a1, float2& a2, float2& a3,
                                         uint4 x, float v) {
    float2 f0 = __half22float2(*(half2*)&x.x);
    float2 f1 = __half22float2(*(half2*)&x.y);
    float2 f2 = __half22float2(*(half2*)&x.z);
    float2 f3 = __half22float2(*(half2*)&x.w);
    a0.x += v * f0.x; a0.y += v * f0.y;
    a1.x += v * f1.x; a1.y += v * f1.y;
    a2.x += v * f2.x; a2.y += v * f2.y;
    a3.x += v * f3.x; a3.y += v * f3.y;
}

__global__ void __launch_bounds__(256) k_spmm(int layer) {
    const uint4* __restrict__ src = (layer & 1) ? g_h1 : g_h0;
    uint4*       __restrict__ dst = (layer & 1) ? g_h0 : g_h1;
    float4*      __restrict__ out = g_o[layer];

    int t    = blockIdx.x * blockDim.x + threadIdx.x;
    int w    = t >> 5;
    int lane = t & 31;
    int row  = w * 4 + (lane >> 3);       // 4 rows per warp
    int ql   = lane & 7;                  // lane within quarter-warp
    if (row >= N_NODES) return;

    int start = g_rowptr[row];
    int end   = g_rowptr[row + 1];

    float2 a0 = {0.f, 0.f}, a1 = {0.f, 0.f}, a2 = {0.f, 0.f}, a3 = {0.f, 0.f};
    int j = start;
    for (; j + 1 < end; j += 2) {
        int2 e0 = __ldg(&g_pedge[j]);
        int2 e1 = __ldg(&g_pedge[j + 1]);
        uint4 x0 = __ldg(&src[e0.x * H_VEC4 + ql]);
        uint4 x1 = __ldg(&src[e1.x * H_VEC4 + ql]);
        fma_edge(a0, a1, a2, a3, x0, __int_as_float(e0.y));
        fma_edge(a0, a1, a2, a3, x1, __int_as_float(e1.y));
    }
    if (j < end) {
        int2 e0 = __ldg(&g_pedge[j]);
        uint4 x0 = __ldg(&src[e0.x * H_VEC4 + ql]);
        fma_edge(a0, a1, a2, a3, x0, __int_as_float(e0.y));
    }

    // fp16 copy for next layer's gathers (stays in L2)
    half2 h0 = __float22half2_rn(a0);
    half2 h1 = __float22half2_rn(a1);
    half2 h2 = __float22half2_rn(a2);
    half2 h3 = __float22half2_rn(a3);
    uint4 hv;
    hv.x = *(unsigned*)&h0; hv.y = *(unsigned*)&h1;
    hv.z = *(unsigned*)&h2; hv.w = *(unsigned*)&h3;
    dst[row * H_VEC4 + ql] = hv;

    // fp32 layer output for the epilogue (streamed; only 32K rows read later)
    float4 f0 = make_float4(a0.x, a0.y, a1.x, a1.y);
    float4 f1 = make_float4(a2.x, a2.y, a3.x, a3.y);
    __stcs(&out[row * D_VEC4 + ql * 2],     f0);
    __stcs(&out[row * D_VEC4 + ql * 2 + 1], f1);
}

// ---------------- epilogue: sum 4 layer embeddings at gathered rows, dot -----
__global__ void k_dot(const float2* __restrict__ ue2, const float2* __restrict__ ie2,
                      const void* __restrict__ uidx_raw, const void* __restrict__ iidx_raw,
                      float* __restrict__ out) {
    int t    = blockIdx.x * blockDim.x + threadIdx.x;
    int w    = t >> 5;
    int lane = t & 31;
    if (w >= BATCH) return;

    long long u, it;
    if (g_is64) {
        u  = ((const long long*)uidx_raw)[w];
        it = ((const long long*)iidx_raw)[w];
    } else {
        u  = ((const int*)uidx_raw)[w];
        it = ((const int*)iidx_raw)[w];
    }

    size_t un = (size_t)u;                       // user node id
    size_t in = (size_t)N_USERS + (size_t)it;    // item node id

    // layer 0 straight from the inputs (exact fp32)
    float2 x = ue2[un * 32 + lane];
    float2 y = ie2[(size_t)it * 32 + lane];
    #pragma unroll
    for (int l = 0; l < 3; l++) {
        const float2* o2 = (const float2*)g_o[l];
        float2 ox = __ldg(&o2[un * 32 + lane]);
        float2 oy = __ldg(&o2[in * 32 + lane]);
        x.x += ox.x; x.y += ox.y;
        y.x += oy.x; y.y += oy.y;
    }

    float p = x.x * y.x + x.y * y.y;
    #pragma unroll
    for (int off = 16; off; off >>= 1)
        p += __shfl_xor_sync(0xffffffffu, p, off);
    if (lane == 0) out[w] = p * (1.0f / 16.0f);   // (sum/4)·(sum/4)
}

// ---------------- launch ------------------------------------------------------
extern "C" void kernel_launch(void* const* d_in, const int* in_sizes, int n_in,
                              void* d_out, int out_size) {
    const float4* ue   = (const float4*)d_in[0];
    const float4* ie   = (const float4*)d_in[1];
    const int*    rows = (const int*)d_in[2];
    const int*    cols = (const int*)d_in[3];
    const float*  vals = (const float*)d_in[4];
    const void*   uidx = d_in[5];
    const void*   iidx = d_in[6];
    float* out = (float*)d_out;

    k_zero_counts<<<(N_NODES + 255) / 256, 256>>>();
    k_init<<<(N_NODES * H_VEC4 + 255) / 256, 256>>>(ue, ie);
    k_detect_idx_width<<<1, 32>>>((const int*)uidx);
    k_hist<<<(NNZ_E / 4 + 255) / 256, 256>>>((const int4*)rows);
    k_scanA<<<NBLK_SCAN, SCAN_BLK>>>();
    k_scanB<<<1, 256>>>();
    k_scanC<<<(N_NODES + 255) / 256, 256>>>();
    k_scatter<<<(NNZ_E / 4 + 255) / 256, 256>>>((const int4*)rows, (const int4*)cols,
                                                (const float4*)vals);

    int spmm_blocks = ((N_NODES + 3) / 4 * 32 + 255) / 256;
    k_spmm<<<spmm_blocks, 256>>>(0);
    k_spmm<<<spmm_blocks, 256>>>(1);
    k_spmm<<<spmm_blocks, 256>>>(2);

    k_dot<<<BATCH * 32 / 256, 256>>>((const float2*)ue, (const float2*)ie, uidx, iidx, out);
}